// round 8
// baseline (speedup 1.0000x reference)
#include <cuda_runtime.h>
#include <cstdint>
#include <cstddef>

// ---------------- problem constants ----------------
#define B_WIN   4096
#define N_TOK   49
#define C_DIM   128
#define NH      4
#define HD      32
#define NWIN    64
#define M_ROWS  (B_WIN * N_TOK)        // 200704
#define SCALE   0.17677669529663687f   // 32^-0.5

// ---------------- scratch (no cudaMalloc allowed) ----------------
__device__ __align__(16) float    g_qkv[(size_t)M_ROWS * 384]; // tf32 BITS, q pre-scaled
__device__ __align__(16) uint32_t g_w2[128 * 128];             // proj_w tf32 bits
__device__ __align__(16) float    g_bm[NWIN * N_TOK * N_TOK];  // bias[rel] + mask

// ---------------- helpers ----------------
__device__ __forceinline__ uint32_t f2tf32(float f) {
    uint32_t r;
    asm("cvt.rna.tf32.f32 %0, %1;" : "=r"(r) : "f"(f));
    return r;
}
__device__ __forceinline__ void mma_tf32(float c[4], const uint32_t a[4], const uint32_t b[2]) {
    asm volatile(
        "mma.sync.aligned.m16n8k8.row.col.f32.tf32.tf32.f32 "
        "{%0,%1,%2,%3}, {%4,%5,%6,%7}, {%8,%9}, {%0,%1,%2,%3};"
        : "+f"(c[0]), "+f"(c[1]), "+f"(c[2]), "+f"(c[3])
        : "r"(a[0]), "r"(a[1]), "r"(a[2]), "r"(a[3]), "r"(b[0]), "r"(b[1]));
}
__device__ __forceinline__ void cp_async16(uint32_t smem_dst, const void* gsrc) {
    asm volatile("cp.async.ca.shared.global [%0], [%1], 16;\n" :: "r"(smem_dst), "l"(gsrc));
}
__device__ __forceinline__ void cp_commit() { asm volatile("cp.async.commit_group;\n"); }
template <int N>
__device__ __forceinline__ void cp_wait() { asm volatile("cp.async.wait_group %0;\n" :: "n"(N)); }

// ---------------- prep: g_w2 = tf32(proj_w); g_bm = bias_table[rel] + mask ----------
__global__ void prep_kernel(const float* __restrict__ mask,
                            const float* __restrict__ bias_table,
                            const int*   __restrict__ rel_index,
                            const float* __restrict__ proj_w)
{
    int idx = blockIdx.x * 256 + threadIdx.x;
    const int n2 = 128 * 128, n3 = NWIN * N_TOK * N_TOK;
    if (idx < n2) {
        g_w2[idx] = f2tf32(proj_w[idx]);
    } else if (idx < n2 + n3) {
        int t = idx - n2;
        g_bm[t] = mask[t] + bias_table[rel_index[t % (N_TOK * N_TOK)]];
    }
}

// ---------------- stage A: r5-proven tf32 GEMM, cp.async double-buffered -------------
// qkv[M,384] = x[M,128] @ qkv_w[128,384] + qkv_b. Tile 128x128, K chunks of 32.
// Output stored as tf32 bits, q (n<128) pre-scaled by SCALE.
#define AS_STRIDE 36
#define BS_STRIDE 136
#define AS_WORDS (128 * AS_STRIDE)
#define BS_WORDS (32 * BS_STRIDE)
#define GEMM_SMEM ((2 * AS_WORDS + 2 * BS_WORDS) * 4)   // 71680 B

__global__ __launch_bounds__(256, 2)
void gemm_qkv_kernel(const float* __restrict__ A,
                     const float* __restrict__ W,
                     const float* __restrict__ bias,
                     float* __restrict__ out)
{
    extern __shared__ float smem[];
    float* As = smem;                 // [2][AS_WORDS]
    float* Bs = smem + 2 * AS_WORDS;  // [2][BS_WORDS]

    const int tid  = threadIdx.x;
    const int lane = tid & 31;
    const int warp = tid >> 5;
    const int wm   = warp >> 2;
    const int wn   = warp & 3;
    const int m0   = blockIdx.x * 128;
    const int n0   = blockIdx.y * 128;

    float acc[4][4][4];
    #pragma unroll
    for (int i = 0; i < 4; i++)
        #pragma unroll
        for (int j = 0; j < 4; j++)
            #pragma unroll
            for (int r = 0; r < 4; r++) acc[i][j][r] = 0.f;

    auto stage_load = [&](int st, int k0) {
        #pragma unroll
        for (int p = 0; p < 4; p++) {
            int idx = tid + p * 256;
            int row = idx >> 3, seg = idx & 7;   // 128 rows x 8 segs (32 floats = K chunk)
            uint32_t dst = (uint32_t)__cvta_generic_to_shared(
                &As[st * AS_WORDS + row * AS_STRIDE + seg * 4]);
            cp_async16(dst, &A[(size_t)(m0 + row) * 128 + k0 + seg * 4]);
        }
        #pragma unroll
        for (int p = 0; p < 4; p++) {
            int idx = tid + p * 256;
            int row = idx >> 5, seg = idx & 31;  // 32 rows x 32 segs (128 floats)
            uint32_t dst = (uint32_t)__cvta_generic_to_shared(
                &Bs[st * BS_WORDS + row * BS_STRIDE + seg * 4]);
            cp_async16(dst, &W[(size_t)(k0 + row) * 384 + n0 + seg * 4]);
        }
        cp_commit();
    };

    stage_load(0, 0);

    #pragma unroll
    for (int ch = 0; ch < 4; ch++) {
        if (ch < 3) stage_load((ch + 1) & 1, (ch + 1) * 32);
        if (ch < 3) cp_wait<1>(); else cp_wait<0>();
        __syncthreads();

        const float* as = &As[(ch & 1) * AS_WORDS];
        const float* bs = &Bs[(ch & 1) * BS_WORDS];

        #pragma unroll
        for (int kk = 0; kk < 4; kk++) {
            const int k = kk * 8;
            uint32_t af[4][4];
            #pragma unroll
            for (int mt = 0; mt < 4; mt++) {
                int row = wm * 64 + mt * 16 + (lane >> 2);
                int col = k + (lane & 3);
                af[mt][0] = f2tf32(as[row * AS_STRIDE + col]);
                af[mt][1] = f2tf32(as[(row + 8) * AS_STRIDE + col]);
                af[mt][2] = f2tf32(as[row * AS_STRIDE + col + 4]);
                af[mt][3] = f2tf32(as[(row + 8) * AS_STRIDE + col + 4]);
            }
            uint32_t bf[4][2];
            #pragma unroll
            for (int nt = 0; nt < 4; nt++) {
                int col = wn * 32 + nt * 8 + (lane >> 2);
                int row = k + (lane & 3);
                bf[nt][0] = f2tf32(bs[row * BS_STRIDE + col]);
                bf[nt][1] = f2tf32(bs[(row + 4) * BS_STRIDE + col]);
            }
            #pragma unroll
            for (int mt = 0; mt < 4; mt++)
                #pragma unroll
                for (int nt = 0; nt < 4; nt++)
                    mma_tf32(acc[mt][nt], af[mt], bf[nt]);
        }
        __syncthreads();
    }

    #pragma unroll
    for (int mt = 0; mt < 4; mt++) {
        #pragma unroll
        for (int nt = 0; nt < 4; nt++) {
            int m = m0 + wm * 64 + mt * 16 + (lane >> 2);
            int n = n0 + wn * 32 + nt * 8 + (lane & 3) * 2;
            float b0 = bias[n], b1 = bias[n + 1];
            float v00 = acc[mt][nt][0] + b0, v01 = acc[mt][nt][1] + b1;
            float v10 = acc[mt][nt][2] + b0, v11 = acc[mt][nt][3] + b1;
            float s0 = (n     < 128) ? SCALE : 1.f;
            float s1 = (n + 1 < 128) ? SCALE : 1.f;
            *(float2*)&out[(size_t)m * 384 + n] = make_float2(
                __uint_as_float(f2tf32(v00 * s0)), __uint_as_float(f2tf32(v01 * s1)));
            *(float2*)&out[(size_t)(m + 8) * 384 + n] = make_float2(
                __uint_as_float(f2tf32(v10 * s0)), __uint_as_float(f2tf32(v11 * s1)));
        }
    }
}

// ---------------- fused attention + proj: one block per window ----------------------
// 8 warps: warp -> (head = warp>>1, m-half = warp&1), owns 32 rows through all phases.
// smem regions (words): X[8704] = K(132) -> V(136) -> Wproj(2x[32][136])
//                       Ss[15360] = 4 heads x [64][60] -> O [64][132]
#define KS_ 132
#define VS_ 136
#define SS_ 60
#define X_WORDS  8704
#define SS_WORDS (4 * 64 * SS_)              // 15360
#define FA_SMEM ((X_WORDS + SS_WORDS) * 4)   // 96256 B

__global__ __launch_bounds__(256, 2)
void attn_proj_kernel(const float* __restrict__ proj_b,
                      float* __restrict__ out)
{
    extern __shared__ uint32_t sm[];
    uint32_t* X  = sm;              // K / V / W staging
    uint32_t* Ss = sm + X_WORDS;    // S per head / later O

    const int w    = blockIdx.x;
    const int tid  = threadIdx.x;
    const int lane = tid & 31;
    const int warp = tid >> 5;
    const int h    = warp >> 1;     // head
    const int mh   = warp & 1;      // m-half

    const uint32_t* qkv = (const uint32_t*)g_qkv + (size_t)w * N_TOK * 384;

    // ---- stage K (rows 0..48, ALL 128 dims) into X stride 132 ----
    for (int t = tid; t < N_TOK * 32; t += 256) {
        int n = t >> 5, seg = t & 31;
        uint32_t dst = (uint32_t)__cvta_generic_to_shared(&X[n * KS_ + seg * 4]);
        cp_async16(dst, &qkv[n * 384 + 128 + seg * 4]);
    }
    for (int t = tid; t < 15 * 128; t += 256) {       // zero pad rows 49..63
        int n = N_TOK + (t >> 7), d = t & 127;
        X[n * KS_ + d] = 0u;
    }
    cp_commit();

    // ---- Q fragments direct from gmem (rows clamped; pad rows discarded later) ----
    const int rA0 = mh * 32 + (lane >> 2);
    uint32_t af[2][4][4];
    #pragma unroll
    for (int mt = 0; mt < 2; mt++) {
        int r0 = min(rA0 + mt * 16,     N_TOK - 1);
        int r1 = min(rA0 + mt * 16 + 8, N_TOK - 1);
        #pragma unroll
        for (int ks = 0; ks < 4; ks++) {
            int col = h * HD + ks * 8 + (lane & 3);
            af[mt][ks][0] = qkv[r0 * 384 + col];
            af[mt][ks][1] = qkv[r1 * 384 + col];
            af[mt][ks][2] = qkv[r0 * 384 + col + 4];
            af[mt][ks][3] = qkv[r1 * 384 + col + 4];
        }
    }
    cp_wait<0>();
    __syncthreads();   // B1: K staged

    // ---- scores: S = qk^T + bm ----
    const float* bm = g_bm + (size_t)(w & (NWIN - 1)) * N_TOK * N_TOK;
    uint32_t* Sh = Ss + h * 64 * SS_;
    #pragma unroll
    for (int nt = 0; nt < 7; nt++) {
        float c[2][4];
        #pragma unroll
        for (int mt = 0; mt < 2; mt++)
            #pragma unroll
            for (int r = 0; r < 4; r++) c[mt][r] = 0.f;
        #pragma unroll
        for (int ks = 0; ks < 4; ks++) {
            int nc = nt * 8 + (lane >> 2);
            int kr = h * HD + ks * 8 + (lane & 3);      // head offset (was missing)
            uint32_t bf[2] = { X[nc * KS_ + kr], X[nc * KS_ + kr + 4] };
            mma_tf32(c[0], af[0][ks], bf);
            mma_tf32(c[1], af[1][ks], bf);
        }
        const int j = nt * 8 + 2 * (lane & 3);
        #pragma unroll
        for (int mt = 0; mt < 2; mt++)
            #pragma unroll
            for (int half = 0; half < 2; half++) {
                int ii = rA0 + mt * 16 + half * 8;
                float o0, o1;
                if (ii < N_TOK) {
                    o0 = (j     < N_TOK) ? c[mt][half * 2]     + __ldg(&bm[ii * N_TOK + j])     : -1e30f;
                    o1 = (j + 1 < N_TOK) ? c[mt][half * 2 + 1] + __ldg(&bm[ii * N_TOK + j + 1]) : -1e30f;
                } else { o0 = 0.f; o1 = 0.f; }
                Sh[ii * SS_ + j]     = __float_as_uint(o0);
                Sh[ii * SS_ + j + 1] = __float_as_uint(o1);
            }
    }
    __syncthreads();   // B2: all K reads done -> X reusable for V

    // ---- stage V (rows 0..48, ALL 128 dims) into X stride 136 ----
    for (int t = tid; t < N_TOK * 32; t += 256) {
        int n = t >> 5, seg = t & 31;
        uint32_t dst = (uint32_t)__cvta_generic_to_shared(&X[n * VS_ + seg * 4]);
        cp_async16(dst, &qkv[n * 384 + 256 + seg * 4]);
    }
    for (int t = tid; t < 15 * 128; t += 256) {
        int n = N_TOK + (t >> 7), d = t & 127;
        X[n * VS_ + d] = 0u;
    }
    cp_commit();

    // ---- softmax on own rows; writeback tf32 bits (P) ----
    {
        const int rend = min(mh * 32 + 32, N_TOK);
        for (int i = mh * 32; i < rend; i++) {
            float v1 = __uint_as_float(Sh[i * SS_ + lane]);
            float v2 = (lane < 24) ? __uint_as_float(Sh[i * SS_ + 32 + lane]) : -1e30f;
            float mx = fmaxf(v1, v2);
            #pragma unroll
            for (int o = 16; o > 0; o >>= 1) mx = fmaxf(mx, __shfl_xor_sync(0xffffffffu, mx, o));
            float e1 = __expf(v1 - mx);
            float e2 = (lane < 24) ? __expf(v2 - mx) : 0.f;
            float s = e1 + e2;
            #pragma unroll
            for (int o = 16; o > 0; o >>= 1) s += __shfl_xor_sync(0xffffffffu, s, o);
            float inv = 1.f / s;
            Sh[i * SS_ + lane] = f2tf32(e1 * inv);
            if (lane < 24) Sh[i * SS_ + 32 + lane] = f2tf32(e2 * inv);
        }
    }
    __syncwarp();

    // ---- load ALL P fragments to regs, then S region becomes O ----
    uint32_t pf[2][7][4];
    #pragma unroll
    for (int mt = 0; mt < 2; mt++) {
        int row = rA0 + mt * 16;
        #pragma unroll
        for (int ks = 0; ks < 7; ks++) {
            int col = ks * 8 + (lane & 3);
            pf[mt][ks][0] = Sh[row * SS_ + col];
            pf[mt][ks][1] = Sh[(row + 8) * SS_ + col];
            pf[mt][ks][2] = Sh[row * SS_ + col + 4];
            pf[mt][ks][3] = Sh[(row + 8) * SS_ + col + 4];
        }
    }
    cp_wait<0>();
    __syncthreads();   // B3: pf loaded everywhere, V staged -> Ss reusable as O

    // ---- O = P @ V into Ss region (stride 132, tf32 bits) ----
    uint32_t* O = Ss;
    #pragma unroll
    for (int mt = 0; mt < 2; mt++) {
        #pragma unroll
        for (int nt = 0; nt < 4; nt++) {
            float c[4] = {0.f, 0.f, 0.f, 0.f};
            #pragma unroll
            for (int ks = 0; ks < 7; ks++) {
                int kr = ks * 8 + (lane & 3);
                int nc = h * HD + nt * 8 + (lane >> 2);
                uint32_t bf[2] = { X[kr * VS_ + nc], X[(kr + 4) * VS_ + nc] };
                mma_tf32(c, pf[mt][ks], bf);
            }
            int r = rA0 + mt * 16;
            int d = h * HD + nt * 8 + 2 * (lane & 3);
            O[r * KS_ + d]           = f2tf32(c[0]);
            O[r * KS_ + d + 1]       = f2tf32(c[1]);
            O[(r + 8) * KS_ + d]     = f2tf32(c[2]);
            O[(r + 8) * KS_ + d + 1] = f2tf32(c[3]);
        }
    }
    __syncthreads();   // B4: O complete, V reads done -> X reusable for W

    // ---- proj: out = O @ proj_w + proj_b ; W double-buffered in X ----
    auto stage_w = [&](int buf, int k0) {
        int row = tid >> 3, ts = tid & 7;     // 32 rows, 8 thr/row
        #pragma unroll
        for (int p = 0; p < 4; p++) {
            int seg = ts + p * 8;             // 32 segs x 16B = full 128-float row
            uint32_t dst = (uint32_t)__cvta_generic_to_shared(
                &X[buf * 32 * VS_ + row * VS_ + seg * 4]);
            cp_async16(dst, &g_w2[(k0 + row) * 128 + seg * 4]);
        }
        cp_commit();
    };

    const int wm = warp >> 2;   // 0..1 (32 rows)
    const int wn = warp & 3;    // 0..3 (32 cols)
    float acc[2][4][4];
    #pragma unroll
    for (int a = 0; a < 2; a++)
        #pragma unroll
        for (int b = 0; b < 4; b++)
            #pragma unroll
            for (int r = 0; r < 4; r++) acc[a][b][r] = 0.f;

    stage_w(0, 0);
    #pragma unroll
    for (int ch = 0; ch < 4; ch++) {
        if (ch < 3) stage_w((ch + 1) & 1, (ch + 1) * 32);
        if (ch < 3) cp_wait<1>(); else cp_wait<0>();
        __syncthreads();
        const uint32_t* ws = &X[(ch & 1) * 32 * VS_];
        #pragma unroll
        for (int kk = 0; kk < 4; kk++) {
            uint32_t oa[2][4];
            #pragma unroll
            for (int mt = 0; mt < 2; mt++) {
                int row = wm * 32 + mt * 16 + (lane >> 2);
                int col = ch * 32 + kk * 8 + (lane & 3);
                oa[mt][0] = O[row * KS_ + col];
                oa[mt][1] = O[(row + 8) * KS_ + col];
                oa[mt][2] = O[row * KS_ + col + 4];
                oa[mt][3] = O[(row + 8) * KS_ + col + 4];
            }
            #pragma unroll
            for (int nt = 0; nt < 4; nt++) {
                int coln = wn * 32 + nt * 8 + (lane >> 2);
                int rowk = kk * 8 + (lane & 3);
                uint32_t bf[2] = { ws[rowk * VS_ + coln], ws[(rowk + 4) * VS_ + coln] };
                mma_tf32(acc[0][nt], oa[0], bf);
                mma_tf32(acc[1][nt], oa[1], bf);
            }
        }
        __syncthreads();
    }

    float* ob = out + (size_t)w * N_TOK * C_DIM;
    #pragma unroll
    for (int mt = 0; mt < 2; mt++) {
        #pragma unroll
        for (int nt = 0; nt < 4; nt++) {
            int n = wn * 32 + nt * 8 + (lane & 3) * 2;
            float b0 = __ldg(&proj_b[n]), b1 = __ldg(&proj_b[n + 1]);
            int m = wm * 32 + mt * 16 + (lane >> 2);
            if (m < N_TOK)
                *(float2*)&ob[m * C_DIM + n] =
                    make_float2(acc[mt][nt][0] + b0, acc[mt][nt][1] + b1);
            if (m + 8 < N_TOK)
                *(float2*)&ob[(m + 8) * C_DIM + n] =
                    make_float2(acc[mt][nt][2] + b0, acc[mt][nt][3] + b1);
        }
    }
}

// ---------------- launch ----------------
extern "C" void kernel_launch(void* const* d_in, const int* in_sizes, int n_in,
                              void* d_out, int out_size)
{
    const float* x          = (const float*)d_in[0];
    const float* mask       = (const float*)d_in[1];
    const float* qkv_w      = (const float*)d_in[2];
    const float* qkv_b      = (const float*)d_in[3];
    const float* proj_w     = (const float*)d_in[4];
    const float* proj_b     = (const float*)d_in[5];
    const float* bias_table = (const float*)d_in[6];
    const int*   rel_index  = (const int*)d_in[7];
    float*       out        = (float*)d_out;

    void* qkv_ptr = nullptr;
    cudaGetSymbolAddress(&qkv_ptr, g_qkv);

    static bool attr_set = false;
    if (!attr_set) {
        cudaFuncSetAttribute(gemm_qkv_kernel,
                             cudaFuncAttributeMaxDynamicSharedMemorySize, GEMM_SMEM);
        cudaFuncSetAttribute(attn_proj_kernel,
                             cudaFuncAttributeMaxDynamicSharedMemorySize, FA_SMEM);
        attr_set = true;
    }

    const int prep_total = 128 * 128 + NWIN * N_TOK * N_TOK;
    prep_kernel<<<(prep_total + 255) / 256, 256>>>(mask, bias_table, rel_index, proj_w);

    gemm_qkv_kernel<<<dim3(M_ROWS / 128, 3), 256, GEMM_SMEM>>>(
        x, qkv_w, qkv_b, (float*)qkv_ptr);

    attn_proj_kernel<<<B_WIN, 256, FA_SMEM>>>(proj_b, out);
}

// round 9
// speedup vs baseline: 1.0590x; 1.0590x over previous
#include <cuda_runtime.h>
#include <cstdint>
#include <cstddef>

// ---------------- problem constants ----------------
#define B_WIN   4096
#define N_TOK   49
#define C_DIM   128
#define NH      4
#define HD      32
#define NWIN    64
#define M_ROWS  (B_WIN * N_TOK)        // 200704
#define SCALE   0.17677669529663687f   // 32^-0.5

// ---------------- scratch (no cudaMalloc allowed) ----------------
__device__ __align__(16) float g_qkv[(size_t)M_ROWS * 384];  // tf32 BITS, q pre-scaled
__device__ __align__(16) float g_att[(size_t)M_ROWS * 128];  // tf32 BITS
__device__ __align__(16) float g_bm[NWIN * N_TOK * N_TOK];   // bias[rel] + mask

// ---------------- helpers ----------------
__device__ __forceinline__ uint32_t f2tf32(float f) {
    uint32_t r;
    asm("cvt.rna.tf32.f32 %0, %1;" : "=r"(r) : "f"(f));
    return r;
}
__device__ __forceinline__ void mma_tf32(float c[4], const uint32_t a[4], const uint32_t b[2]) {
    asm volatile(
        "mma.sync.aligned.m16n8k8.row.col.f32.tf32.tf32.f32 "
        "{%0,%1,%2,%3}, {%4,%5,%6,%7}, {%8,%9}, {%0,%1,%2,%3};"
        : "+f"(c[0]), "+f"(c[1]), "+f"(c[2]), "+f"(c[3])
        : "r"(a[0]), "r"(a[1]), "r"(a[2]), "r"(a[3]), "r"(b[0]), "r"(b[1]));
}
__device__ __forceinline__ void cp_async16(uint32_t smem_dst, const void* gsrc) {
    asm volatile("cp.async.ca.shared.global [%0], [%1], 16;\n" :: "r"(smem_dst), "l"(gsrc));
}
__device__ __forceinline__ void cp_commit() { asm volatile("cp.async.commit_group;\n"); }
template <int N>
__device__ __forceinline__ void cp_wait() { asm volatile("cp.async.wait_group %0;\n" :: "n"(N)); }

// ---------------- pre-kernel: g_bm = bias_table[rel_index] + mask ----------------
__global__ void bm_kernel(const float* __restrict__ mask,
                          const float* __restrict__ bias_table,
                          const int*   __restrict__ rel_index)
{
    int idx = blockIdx.x * 256 + threadIdx.x;
    if (idx >= NWIN * N_TOK * N_TOK) return;
    int r = idx % (N_TOK * N_TOK);
    g_bm[idx] = mask[idx] + bias_table[rel_index[r]];
}

// ---------------- tf32 GEMM, cp.async double-buffered --------------------------------
// out[M,NCOLS] = A[M,128] @ W[128,NCOLS] + bias. Tile 128x128, K chunks of 32.
// Grid: (n_blocks, m_blocks) -> consecutive blocks share the same A tile (L2 reuse).
// QKV_OUT: store tf32 bits, q (n<128) pre-scaled. A_TF32: A already holds tf32 bits.
#define AS_STRIDE 36
#define BS_STRIDE 136
#define AS_WORDS (128 * AS_STRIDE)
#define BS_WORDS (32 * BS_STRIDE)
#define GEMM_SMEM ((2 * AS_WORDS + 2 * BS_WORDS) * 4)   // 71680 B

template <int NCOLS, bool QKV_OUT, bool A_TF32>
__global__ __launch_bounds__(256, 2)
void gemm_tc_kernel(const float* __restrict__ A,
                    const float* __restrict__ W,
                    const float* __restrict__ bias,
                    float* __restrict__ out)
{
    extern __shared__ float smem[];
    float* As = smem;                 // [2][AS_WORDS]
    float* Bs = smem + 2 * AS_WORDS;  // [2][BS_WORDS]

    const int tid  = threadIdx.x;
    const int lane = tid & 31;
    const int warp = tid >> 5;
    const int wm   = warp >> 2;
    const int wn   = warp & 3;
    const int m0   = blockIdx.y * 128;   // m from Y: adjacent X-blocks reuse A tile
    const int n0   = blockIdx.x * 128;

    float acc[4][4][4];
    #pragma unroll
    for (int i = 0; i < 4; i++)
        #pragma unroll
        for (int j = 0; j < 4; j++)
            #pragma unroll
            for (int r = 0; r < 4; r++) acc[i][j][r] = 0.f;

    auto stage_load = [&](int st, int k0) {
        #pragma unroll
        for (int p = 0; p < 4; p++) {
            int idx = tid + p * 256;
            int row = idx >> 3, seg = idx & 7;    // 128 rows x 8 segs (32 floats)
            uint32_t dst = (uint32_t)__cvta_generic_to_shared(
                &As[st * AS_WORDS + row * AS_STRIDE + seg * 4]);
            cp_async16(dst, &A[(size_t)(m0 + row) * 128 + k0 + seg * 4]);
        }
        #pragma unroll
        for (int p = 0; p < 4; p++) {
            int idx = tid + p * 256;
            int row = idx >> 5, seg = idx & 31;   // 32 rows x 32 segs (128 floats)
            uint32_t dst = (uint32_t)__cvta_generic_to_shared(
                &Bs[st * BS_WORDS + row * BS_STRIDE + seg * 4]);
            cp_async16(dst, &W[(size_t)(k0 + row) * NCOLS + n0 + seg * 4]);
        }
        cp_commit();
    };

    stage_load(0, 0);

    #pragma unroll
    for (int ch = 0; ch < 4; ch++) {
        if (ch < 3) stage_load((ch + 1) & 1, (ch + 1) * 32);
        if (ch < 3) cp_wait<1>(); else cp_wait<0>();
        __syncthreads();

        const float* as = &As[(ch & 1) * AS_WORDS];
        const float* bs = &Bs[(ch & 1) * BS_WORDS];

        #pragma unroll
        for (int kk = 0; kk < 4; kk++) {
            const int k = kk * 8;
            uint32_t af[4][4];
            #pragma unroll
            for (int mt = 0; mt < 4; mt++) {
                int row = wm * 64 + mt * 16 + (lane >> 2);
                int col = k + (lane & 3);
                if (A_TF32) {
                    af[mt][0] = __float_as_uint(as[row * AS_STRIDE + col]);
                    af[mt][1] = __float_as_uint(as[(row + 8) * AS_STRIDE + col]);
                    af[mt][2] = __float_as_uint(as[row * AS_STRIDE + col + 4]);
                    af[mt][3] = __float_as_uint(as[(row + 8) * AS_STRIDE + col + 4]);
                } else {
                    af[mt][0] = f2tf32(as[row * AS_STRIDE + col]);
                    af[mt][1] = f2tf32(as[(row + 8) * AS_STRIDE + col]);
                    af[mt][2] = f2tf32(as[row * AS_STRIDE + col + 4]);
                    af[mt][3] = f2tf32(as[(row + 8) * AS_STRIDE + col + 4]);
                }
            }
            uint32_t bf[4][2];
            #pragma unroll
            for (int nt = 0; nt < 4; nt++) {
                int col = wn * 32 + nt * 8 + (lane >> 2);
                int row = k + (lane & 3);
                bf[nt][0] = f2tf32(bs[row * BS_STRIDE + col]);
                bf[nt][1] = f2tf32(bs[(row + 4) * BS_STRIDE + col]);
            }
            #pragma unroll
            for (int mt = 0; mt < 4; mt++)
                #pragma unroll
                for (int nt = 0; nt < 4; nt++)
                    mma_tf32(acc[mt][nt], af[mt], bf[nt]);
        }
        __syncthreads();
    }

    #pragma unroll
    for (int mt = 0; mt < 4; mt++) {
        #pragma unroll
        for (int nt = 0; nt < 4; nt++) {
            int m = m0 + wm * 64 + mt * 16 + (lane >> 2);
            int n = n0 + wn * 32 + nt * 8 + (lane & 3) * 2;
            float b0 = bias[n], b1 = bias[n + 1];
            float v00 = acc[mt][nt][0] + b0, v01 = acc[mt][nt][1] + b1;
            float v10 = acc[mt][nt][2] + b0, v11 = acc[mt][nt][3] + b1;
            if (QKV_OUT) {
                float s0 = (n     < 128) ? SCALE : 1.f;
                float s1 = (n + 1 < 128) ? SCALE : 1.f;
                *(float2*)&out[(size_t)m * NCOLS + n] = make_float2(
                    __uint_as_float(f2tf32(v00 * s0)), __uint_as_float(f2tf32(v01 * s1)));
                *(float2*)&out[(size_t)(m + 8) * NCOLS + n] = make_float2(
                    __uint_as_float(f2tf32(v10 * s0)), __uint_as_float(f2tf32(v11 * s1)));
            } else {
                *(float2*)&out[(size_t)m * NCOLS + n] = make_float2(v00, v01);
                *(float2*)&out[(size_t)(m + 8) * NCOLS + n] = make_float2(v10, v11);
            }
        }
    }
}

// ---------------- tensor-core window attention (r5-proven), tf32 O out --------------
#define QS 36
#define VS 40
#define SS 60

__global__ __launch_bounds__(128)
void attn_tc_kernel()
{
    const int w = blockIdx.x;
    const int h = blockIdx.y;

    __shared__ __align__(16) uint32_t Qs[64 * QS];
    __shared__ __align__(16) uint32_t Ks[64 * QS];
    __shared__ __align__(16) uint32_t Vs[64 * VS];
    __shared__ __align__(16) uint32_t S [64 * SS];

    const int tid  = threadIdx.x;
    const int lane = tid & 31;
    const int warp = tid >> 5;

    // ---- async-stage q/k/v head slices (tf32 bits, q pre-scaled) ----
    const float* bq = g_qkv + (size_t)w * N_TOK * 384 + h * HD;
    for (int t = tid; t < N_TOK * 8 * 3; t += 128) {
        int tt = t / (N_TOK * 8);
        int rem = t - tt * (N_TOK * 8);
        int n = rem >> 3, seg = rem & 7;           // 8 segs x 16B = 32 dims (head slice)
        const float* src = bq + n * 384 + tt * 128 + seg * 4;
        uint32_t dst;
        if (tt == 0)      dst = (uint32_t)__cvta_generic_to_shared(&Qs[n * QS + seg * 4]);
        else if (tt == 1) dst = (uint32_t)__cvta_generic_to_shared(&Ks[n * QS + seg * 4]);
        else              dst = (uint32_t)__cvta_generic_to_shared(&Vs[n * VS + seg * 4]);
        cp_async16(dst, src);
    }
    cp_commit();
    for (int t = tid; t < 15 * HD; t += 128) {     // zero pad rows 49..63
        int n = N_TOK + (t >> 5), d = t & 31;
        Qs[n * QS + d] = 0u;
        Ks[n * QS + d] = 0u;
        Vs[n * VS + d] = 0u;
    }
    cp_wait<0>();
    __syncthreads();   // only block barrier

    // ---- scores for this warp's 16 rows ----
    const float* bm = g_bm + (size_t)(w & (NWIN - 1)) * N_TOK * N_TOK;
    const int rA = warp * 16 + (lane >> 2);
    {
        uint32_t af[4][4];
        #pragma unroll
        for (int ks = 0; ks < 4; ks++) {
            int col = ks * 8 + (lane & 3);
            af[ks][0] = Qs[rA * QS + col];
            af[ks][1] = Qs[(rA + 8) * QS + col];
            af[ks][2] = Qs[rA * QS + col + 4];
            af[ks][3] = Qs[(rA + 8) * QS + col + 4];
        }
        #pragma unroll
        for (int nt = 0; nt < 7; nt++) {
            float c[4] = {0.f, 0.f, 0.f, 0.f};
            #pragma unroll
            for (int ks = 0; ks < 4; ks++) {
                int nc = nt * 8 + (lane >> 2);
                int kr = ks * 8 + (lane & 3);
                uint32_t bf[2] = { Ks[nc * QS + kr], Ks[nc * QS + kr + 4] };
                mma_tf32(c, af[ks], bf);
            }
            const int j = nt * 8 + 2 * (lane & 3);
            #pragma unroll
            for (int half = 0; half < 2; half++) {
                int ii = rA + half * 8;
                float o0, o1;
                if (ii < N_TOK) {
                    o0 = (j     < N_TOK) ? c[half * 2]     + __ldg(&bm[ii * N_TOK + j])     : -1e30f;
                    o1 = (j + 1 < N_TOK) ? c[half * 2 + 1] + __ldg(&bm[ii * N_TOK + j + 1]) : -1e30f;
                } else { o0 = 0.f; o1 = 0.f; }
                S[ii * SS + j]     = __float_as_uint(o0);
                S[ii * SS + j + 1] = __float_as_uint(o1);
            }
        }
    }
    __syncwarp();

    // ---- softmax on own rows, writeback tf32 bits (P) ----
    {
        const int rend = min(warp * 16 + 16, N_TOK);
        for (int i = warp * 16; i < rend; i++) {
            float v1 = __uint_as_float(S[i * SS + lane]);
            float v2 = (lane < 24) ? __uint_as_float(S[i * SS + 32 + lane]) : -1e30f;
            float mx = fmaxf(v1, v2);
            #pragma unroll
            for (int o = 16; o > 0; o >>= 1) mx = fmaxf(mx, __shfl_xor_sync(0xffffffffu, mx, o));
            float e1 = __expf(v1 - mx);
            float e2 = (lane < 24) ? __expf(v2 - mx) : 0.f;
            float s = e1 + e2;
            #pragma unroll
            for (int o = 16; o > 0; o >>= 1) s += __shfl_xor_sync(0xffffffffu, s, o);
            float inv = 1.f / s;
            S[i * SS + lane] = f2tf32(e1 * inv);
            if (lane < 24) S[i * SS + 32 + lane] = f2tf32(e2 * inv);
        }
    }
    __syncwarp();

    // ---- O = P @ V for this warp's rows, store tf32 bits to g_att ----
    {
        uint32_t pf[7][4];
        #pragma unroll
        for (int ks = 0; ks < 7; ks++) {
            int col = ks * 8 + (lane & 3);
            pf[ks][0] = S[rA * SS + col];
            pf[ks][1] = S[(rA + 8) * SS + col];
            pf[ks][2] = S[rA * SS + col + 4];
            pf[ks][3] = S[(rA + 8) * SS + col + 4];
        }
        float* outb = g_att + (size_t)w * N_TOK * C_DIM + h * HD;
        #pragma unroll
        for (int nt = 0; nt < 4; nt++) {
            float c[4] = {0.f, 0.f, 0.f, 0.f};
            #pragma unroll
            for (int ks = 0; ks < 7; ks++) {
                int kr = ks * 8 + (lane & 3);
                int nc = nt * 8 + (lane >> 2);
                uint32_t bf[2] = { Vs[kr * VS + nc], Vs[(kr + 4) * VS + nc] };
                mma_tf32(c, pf[ks], bf);
            }
            const int d = nt * 8 + 2 * (lane & 3);
            if (rA < N_TOK)
                *(float2*)&outb[rA * C_DIM + d] = make_float2(
                    __uint_as_float(f2tf32(c[0])), __uint_as_float(f2tf32(c[1])));
            if (rA + 8 < N_TOK)
                *(float2*)&outb[(rA + 8) * C_DIM + d] = make_float2(
                    __uint_as_float(f2tf32(c[2])), __uint_as_float(f2tf32(c[3])));
        }
    }
}

// ---------------- launch ----------------
extern "C" void kernel_launch(void* const* d_in, const int* in_sizes, int n_in,
                              void* d_out, int out_size)
{
    const float* x          = (const float*)d_in[0];
    const float* mask       = (const float*)d_in[1];
    const float* qkv_w      = (const float*)d_in[2];
    const float* qkv_b      = (const float*)d_in[3];
    const float* proj_w     = (const float*)d_in[4];
    const float* proj_b     = (const float*)d_in[5];
    const float* bias_table = (const float*)d_in[6];
    const int*   rel_index  = (const int*)d_in[7];
    float*       out        = (float*)d_out;

    void* qkv_ptr = nullptr;
    void* att_ptr = nullptr;
    cudaGetSymbolAddress(&qkv_ptr, g_qkv);
    cudaGetSymbolAddress(&att_ptr, g_att);

    static bool attr_set = false;
    if (!attr_set) {
        cudaFuncSetAttribute((const void*)gemm_tc_kernel<384, true, false>,
                             cudaFuncAttributeMaxDynamicSharedMemorySize, GEMM_SMEM);
        cudaFuncSetAttribute((const void*)gemm_tc_kernel<128, false, true>,
                             cudaFuncAttributeMaxDynamicSharedMemorySize, GEMM_SMEM);
        attr_set = true;
    }

    // bias+mask fusion table
    bm_kernel<<<(NWIN * N_TOK * N_TOK + 255) / 256, 256>>>(mask, bias_table, rel_index);

    // Stage A: qkv (tf32 bits, q pre-scaled). Grid (n, m): A-tile L2 reuse.
    gemm_tc_kernel<384, true, false><<<dim3(384 / 128, M_ROWS / 128), 256, GEMM_SMEM>>>(
        x, qkv_w, qkv_b, (float*)qkv_ptr);

    // Stage B: tensor-core windowed attention (O stored as tf32 bits)
    attn_tc_kernel<<<dim3(B_WIN, NH), 128>>>();

    // Stage C: out = att @ proj_w + proj_b (A already tf32 bits)
    gemm_tc_kernel<128, false, true><<<dim3(1, M_ROWS / 128), 256, GEMM_SMEM>>>(
        (const float*)att_ptr, proj_w, proj_b, out);
}